// round 3
// baseline (speedup 1.0000x reference)
#include <cuda_runtime.h>
#include <math_constants.h>

#define QLEN  65536
#define EDIM  256
#define NH    8
#define DHEAD 32
#define KNBR  16

// Scratch (allocation-free rule: __device__ globals)
__device__ float g_q[(size_t)QLEN * EDIM];
__device__ float g_k[(size_t)QLEN * EDIM];
__device__ float g_v[(size_t)QLEN * EDIM];
__device__ float g_attn[(size_t)QLEN * EDIM];

// ---------------------------------------------------------------------------
// SGEMM core: C[M,256] = (A[M,256] @ W[256,256]^T + bias) * scale
// Block tile 128x128, BK=16, 256 threads, 8x8 microtile per thread.
// Grid: x = N/128 (=2), y = M/128. M,N,K all multiples of tile sizes here.
// ---------------------------------------------------------------------------
__device__ __forceinline__ void gemm256(const float* __restrict__ A,
                                        const float* __restrict__ W,
                                        const float* __restrict__ bias,
                                        float* __restrict__ C,
                                        float scale)
{
    __shared__ float As[16][132];   // transposed, padded (528B rows, 16B-aligned)
    __shared__ float Bs[16][132];

    const int tid = threadIdx.x;
    const int tx = tid & 15;          // 0..15 -> N direction
    const int ty = tid >> 4;          // 0..15 -> M direction
    const int mBase = blockIdx.y * 128;
    const int nBase = blockIdx.x * 128;
    const int loadRow = tid >> 2;     // 0..63
    const int loadCol = (tid & 3) << 2; // 0,4,8,12

    float acc[8][8];
#pragma unroll
    for (int i = 0; i < 8; i++)
#pragma unroll
        for (int j = 0; j < 8; j++) acc[i][j] = 0.f;

    for (int k0 = 0; k0 < 256; k0 += 16) {
#pragma unroll
        for (int r = 0; r < 2; r++) {
            int row = loadRow + r * 64;
            float4 av = *(const float4*)(A + (size_t)(mBase + row) * 256 + k0 + loadCol);
            As[loadCol + 0][row] = av.x;
            As[loadCol + 1][row] = av.y;
            As[loadCol + 2][row] = av.z;
            As[loadCol + 3][row] = av.w;
            float4 wv = *(const float4*)(W + (size_t)(nBase + row) * 256 + k0 + loadCol);
            Bs[loadCol + 0][row] = wv.x;
            Bs[loadCol + 1][row] = wv.y;
            Bs[loadCol + 2][row] = wv.z;
            Bs[loadCol + 3][row] = wv.w;
        }
        __syncthreads();

#pragma unroll
        for (int kk = 0; kk < 16; kk++) {
            float a[8], b[8];
            *(float4*)&a[0] = *(const float4*)&As[kk][ty * 8];
            *(float4*)&a[4] = *(const float4*)&As[kk][ty * 8 + 4];
            *(float4*)&b[0] = *(const float4*)&Bs[kk][tx * 8];
            *(float4*)&b[4] = *(const float4*)&Bs[kk][tx * 8 + 4];
#pragma unroll
            for (int i = 0; i < 8; i++)
#pragma unroll
                for (int j = 0; j < 8; j++)
                    acc[i][j] = fmaf(a[i], b[j], acc[i][j]);
        }
        __syncthreads();
    }

    // Epilogue: add bias, scale, vectorized store
#pragma unroll
    for (int i = 0; i < 8; i++) {
        int row = mBase + ty * 8 + i;
#pragma unroll
        for (int j = 0; j < 8; j += 4) {
            int col = nBase + tx * 8 + j;
            float4 o;
            o.x = (acc[i][j + 0] + bias[col + 0]) * scale;
            o.y = (acc[i][j + 1] + bias[col + 1]) * scale;
            o.z = (acc[i][j + 2] + bias[col + 2]) * scale;
            o.w = (acc[i][j + 3] + bias[col + 3]) * scale;
            *(float4*)(C + (size_t)row * 256 + col) = o;
        }
    }
}

// Fused QKV projection: blockIdx.z selects which projection.
__global__ __launch_bounds__(256, 2)
void qkv_proj_kernel(const float* __restrict__ q_in,
                     const float* __restrict__ k_in,
                     const float* __restrict__ v_in,
                     const float* __restrict__ Wall,
                     const float* __restrict__ ball)
{
    const float* A;
    const float* W;
    const float* b;
    float* C;
    float scale;
    if (blockIdx.z == 0) {
        A = q_in; W = Wall;               b = ball;       C = g_q;
        scale = 0.17677669529663687f;     // 1/sqrt(32), folded into q
    } else if (blockIdx.z == 1) {
        A = k_in; W = Wall + 256 * 256;   b = ball + 256; C = g_k; scale = 1.f;
    } else {
        A = v_in; W = Wall + 512 * 256;   b = ball + 512; C = g_v; scale = 1.f;
    }
    gemm256(A, W, b, C, scale);
}

__global__ __launch_bounds__(256, 2)
void outproj_kernel(const float* __restrict__ Wout,
                    const float* __restrict__ bout,
                    float* __restrict__ out)
{
    gemm256(g_attn, Wout, bout, out, 1.f);
}

// ---------------------------------------------------------------------------
// Attention: 1 block per query, warp h = head h, lane = dim within head.
// Gathers k/v rows (coalesced 128B per neighbor per head), register softmax
// over 16 neighbors, writes attn output + cross-head-averaged weights.
// ---------------------------------------------------------------------------
__global__ __launch_bounds__(256)
void attn_kernel(const int* __restrict__ idx,
                 float* __restrict__ w_out,
                 int write_w)
{
    const int q = blockIdx.x;
    const int lane = threadIdx.x & 31;
    const int warp = threadIdx.x >> 5;      // head
    const int base = warp * DHEAD + lane;   // offset within E

    __shared__ float sw[NH][KNBR];

    int myIdx = (lane < KNBR) ? idx[q * KNBR + lane] : -1;
    float qv = g_q[(size_t)q * EDIM + base];

    float logit[KNBR];
#pragma unroll
    for (int j = 0; j < KNBR; j++) {
        int kj = __shfl_sync(0xffffffffu, myIdx, j);
        float kv = (kj >= 0) ? g_k[(size_t)kj * EDIM + base] : 0.f;
        float p = qv * kv;
        p += __shfl_xor_sync(0xffffffffu, p, 16);
        p += __shfl_xor_sync(0xffffffffu, p, 8);
        p += __shfl_xor_sync(0xffffffffu, p, 4);
        p += __shfl_xor_sync(0xffffffffu, p, 2);
        p += __shfl_xor_sync(0xffffffffu, p, 1);
        logit[j] = (kj >= 0) ? p : -CUDART_INF_F;
    }

    // softmax over 16 neighbors (all lanes hold identical logits)
    float m = logit[0];
#pragma unroll
    for (int j = 1; j < KNBR; j++) m = fmaxf(m, logit[j]);

    float w[KNBR];
    if (m == -CUDART_INF_F) {
        // all neighbors invalid -> reference zeroes the weights entirely
#pragma unroll
        for (int j = 0; j < KNBR; j++) w[j] = 0.f;
    } else {
        float s = 0.f;
#pragma unroll
        for (int j = 0; j < KNBR; j++) {
            w[j] = __expf(logit[j] - m);   // exp(-inf)=0 handles invalid slots
            s += w[j];
        }
        float inv = 1.f / s;
#pragma unroll
        for (int j = 0; j < KNBR; j++) w[j] *= inv;
    }

    // weighted value gather
    float o = 0.f;
#pragma unroll
    for (int j = 0; j < KNBR; j++) {
        int kj = __shfl_sync(0xffffffffu, myIdx, j);
        float vv = (kj >= 0) ? g_v[(size_t)kj * EDIM + base] : 0.f;
        o = fmaf(w[j], vv, o);
    }
    g_attn[(size_t)q * EDIM + base] = o;

    if (write_w) {
        // each warp deposits its 16 weights (lane j writes w[j], unrolled -> static idx)
#pragma unroll
        for (int j = 0; j < KNBR; j++)
            if (lane == j) sw[warp][j] = w[j];
        __syncthreads();
        if (threadIdx.x < KNBR) {
            float acc = 0.f;
#pragma unroll
            for (int h = 0; h < NH; h++) acc += sw[h][threadIdx.x];
            w_out[q * KNBR + threadIdx.x] = acc * 0.125f;  // /NH
        }
    }
}

// ---------------------------------------------------------------------------
extern "C" void kernel_launch(void* const* d_in, const int* in_sizes, int n_in,
                              void* d_out, int out_size)
{
    const float* q_in = (const float*)d_in[0];
    const float* k_in = (const float*)d_in[1];
    const float* v_in = (const float*)d_in[2];
    const int*   idx  = (const int*)  d_in[3];
    const float* Wall = (const float*)d_in[4];
    const float* ball = (const float*)d_in[5];
    const float* Wout = (const float*)d_in[6];
    const float* bout = (const float*)d_in[7];
    float* out = (float*)d_out;

    // 1) fused q/k/v projections
    dim3 gproj(2, 512, 3);
    qkv_proj_kernel<<<gproj, 256>>>(q_in, k_in, v_in, Wall, ball);

    // 2) gather attention (+ averaged weights, second output)
    int write_w = (out_size >= QLEN * (EDIM + KNBR)) ? 1 : 0;
    attn_kernel<<<QLEN, 256>>>(idx, out + (size_t)QLEN * EDIM, write_w);

    // 3) output projection -> d_out[0 : Q*E]
    dim3 gout(2, 512, 1);
    outproj_kernel<<<gout, 256>>>(Wout, bout, out);
}

// round 4
// speedup vs baseline: 1.6101x; 1.6101x over previous
#include <cuda_runtime.h>
#include <math_constants.h>
#include <cstdint>

#define QLEN  65536
#define EDIM  256
#define NH    8
#define DHEAD 32
#define KNBR  16

// Scratch (allocation-free rule: __device__ globals)
__device__ float g_q[(size_t)QLEN * EDIM];
__device__ float g_k[(size_t)QLEN * EDIM];
__device__ float g_v[(size_t)QLEN * EDIM];
__device__ float g_attn[(size_t)QLEN * EDIM];

// ---------------------------------------------------------------------------
// TF32 tensor-core GEMM: C[M,256] = (A[M,256] @ W[256,256]^T + bias) * scale
// Block tile 128x128, BK=32, 256 threads = 8 warps (4 in M x 2 in N).
// Warp tile 32x64 = 2x8 m16n8k8 atoms. fp32 accumulate, fp32 epilogue.
// ---------------------------------------------------------------------------
#define BK 32
#define SSTRIDE 36   // padded row stride (words): bank = (4g+t)%32, conflict-free

__device__ __forceinline__ uint32_t f2tf32(float x) {
    uint32_t r;
    asm("cvt.rna.tf32.f32 %0, %1;" : "=r"(r) : "f"(x));
    return r;
}

__device__ __forceinline__ void mma_tf32(float c[4], const uint32_t a[4], const uint32_t b[2]) {
    asm volatile(
        "mma.sync.aligned.m16n8k8.row.col.f32.tf32.tf32.f32 "
        "{%0,%1,%2,%3}, {%4,%5,%6,%7}, {%8,%9}, {%0,%1,%2,%3};"
        : "+f"(c[0]), "+f"(c[1]), "+f"(c[2]), "+f"(c[3])
        : "r"(a[0]), "r"(a[1]), "r"(a[2]), "r"(a[3]), "r"(b[0]), "r"(b[1]));
}

__device__ __forceinline__ void gemm256_tf32(const float* __restrict__ A,
                                             const float* __restrict__ W,
                                             const float* __restrict__ bias,
                                             float* __restrict__ C,
                                             float scale)
{
    __shared__ uint32_t As[128 * SSTRIDE];   // [m][k], tf32 bits
    __shared__ uint32_t Bs[128 * SSTRIDE];   // [n][k], tf32 bits

    const int tid   = threadIdx.x;
    const int lane  = tid & 31;
    const int warp  = tid >> 5;
    const int g     = lane >> 2;     // groupID 0..7
    const int t     = lane & 3;      // thread-in-group 0..3
    const int warpM = warp >> 1;     // 0..3  -> M offset warpM*32
    const int warpN = warp & 1;      // 0..1  -> N offset warpN*64

    const int mBase = blockIdx.y * 128;
    const int nBase = blockIdx.x * 128;

    // gmem->smem mapping: 8 float4 per 32-float k-row, 32 rows per pass, 4 passes
    const int kq  = tid & 7;         // float4 index within k-row
    const int row = tid >> 3;        // 0..31

    float acc[2][8][4];
#pragma unroll
    for (int ma = 0; ma < 2; ma++)
#pragma unroll
        for (int na = 0; na < 8; na++)
#pragma unroll
            for (int i = 0; i < 4; i++) acc[ma][na][i] = 0.f;

    for (int kc = 0; kc < 256; kc += BK) {
        // ---- load tiles, convert to tf32, store to smem ----
#pragma unroll
        for (int p = 0; p < 4; p++) {
            int r = row + p * 32;
            float4 av = *(const float4*)(A + (size_t)(mBase + r) * 256 + kc + kq * 4);
            uint32_t* da = &As[r * SSTRIDE + kq * 4];
            da[0] = f2tf32(av.x); da[1] = f2tf32(av.y);
            da[2] = f2tf32(av.z); da[3] = f2tf32(av.w);
            float4 wv = *(const float4*)(W + (size_t)(nBase + r) * 256 + kc + kq * 4);
            uint32_t* db = &Bs[r * SSTRIDE + kq * 4];
            db[0] = f2tf32(wv.x); db[1] = f2tf32(wv.y);
            db[2] = f2tf32(wv.z); db[3] = f2tf32(wv.w);
        }
        __syncthreads();

        // ---- 4 k-steps of 8 ----
#pragma unroll
        for (int ks = 0; ks < 4; ks++) {
            const int k0 = ks * 8;
            uint32_t a[2][4];
#pragma unroll
            for (int ma = 0; ma < 2; ma++) {
                const uint32_t* pa = &As[(warpM * 32 + ma * 16 + g) * SSTRIDE + k0 + t];
                a[ma][0] = pa[0];
                a[ma][1] = pa[8 * SSTRIDE];
                a[ma][2] = pa[4];
                a[ma][3] = pa[8 * SSTRIDE + 4];
            }
            uint32_t b[8][2];
#pragma unroll
            for (int na = 0; na < 8; na++) {
                const uint32_t* pb = &Bs[(warpN * 64 + na * 8 + g) * SSTRIDE + k0 + t];
                b[na][0] = pb[0];
                b[na][1] = pb[4];
            }
#pragma unroll
            for (int ma = 0; ma < 2; ma++)
#pragma unroll
                for (int na = 0; na < 8; na++)
                    mma_tf32(acc[ma][na], a[ma], b[na]);
        }
        __syncthreads();
    }

    // ---- epilogue: bias + scale, float2 stores (sector-packed) ----
#pragma unroll
    for (int ma = 0; ma < 2; ma++) {
        int row0 = mBase + warpM * 32 + ma * 16 + g;
#pragma unroll
        for (int na = 0; na < 8; na++) {
            int col = nBase + warpN * 64 + na * 8 + t * 2;
            float2 bb = *(const float2*)(bias + col);
            float2 o0, o1;
            o0.x = (acc[ma][na][0] + bb.x) * scale;
            o0.y = (acc[ma][na][1] + bb.y) * scale;
            o1.x = (acc[ma][na][2] + bb.x) * scale;
            o1.y = (acc[ma][na][3] + bb.y) * scale;
            *(float2*)(C + (size_t)row0 * 256 + col) = o0;
            *(float2*)(C + (size_t)(row0 + 8) * 256 + col) = o1;
        }
    }
}

// Fused QKV projection: blockIdx.z selects which projection.
__global__ __launch_bounds__(256, 2)
void qkv_proj_kernel(const float* __restrict__ q_in,
                     const float* __restrict__ k_in,
                     const float* __restrict__ v_in,
                     const float* __restrict__ Wall,
                     const float* __restrict__ ball)
{
    const float* A;
    const float* W;
    const float* b;
    float* C;
    float scale;
    if (blockIdx.z == 0) {
        A = q_in; W = Wall;               b = ball;       C = g_q;
        scale = 0.17677669529663687f;     // 1/sqrt(32), folded into q
    } else if (blockIdx.z == 1) {
        A = k_in; W = Wall + 256 * 256;   b = ball + 256; C = g_k; scale = 1.f;
    } else {
        A = v_in; W = Wall + 512 * 256;   b = ball + 512; C = g_v; scale = 1.f;
    }
    gemm256_tf32(A, W, b, C, scale);
}

__global__ __launch_bounds__(256, 2)
void outproj_kernel(const float* __restrict__ Wout,
                    const float* __restrict__ bout,
                    float* __restrict__ out)
{
    gemm256_tf32(g_attn, Wout, bout, out, 1.f);
}

// ---------------------------------------------------------------------------
// Attention: 1 block per query, warp h = head h, lane = dim within head.
// ---------------------------------------------------------------------------
__global__ __launch_bounds__(256)
void attn_kernel(const int* __restrict__ idx,
                 float* __restrict__ w_out,
                 int write_w)
{
    const int q = blockIdx.x;
    const int lane = threadIdx.x & 31;
    const int warp = threadIdx.x >> 5;      // head
    const int base = warp * DHEAD + lane;   // offset within E

    __shared__ float sw[NH][KNBR];

    int myIdx = (lane < KNBR) ? idx[q * KNBR + lane] : -1;
    float qv = g_q[(size_t)q * EDIM + base];

    float logit[KNBR];
#pragma unroll
    for (int j = 0; j < KNBR; j++) {
        int kj = __shfl_sync(0xffffffffu, myIdx, j);
        float kv = (kj >= 0) ? g_k[(size_t)kj * EDIM + base] : 0.f;
        float p = qv * kv;
        p += __shfl_xor_sync(0xffffffffu, p, 16);
        p += __shfl_xor_sync(0xffffffffu, p, 8);
        p += __shfl_xor_sync(0xffffffffu, p, 4);
        p += __shfl_xor_sync(0xffffffffu, p, 2);
        p += __shfl_xor_sync(0xffffffffu, p, 1);
        logit[j] = (kj >= 0) ? p : -CUDART_INF_F;
    }

    float m = logit[0];
#pragma unroll
    for (int j = 1; j < KNBR; j++) m = fmaxf(m, logit[j]);

    float w[KNBR];
    if (m == -CUDART_INF_F) {
#pragma unroll
        for (int j = 0; j < KNBR; j++) w[j] = 0.f;
    } else {
        float s = 0.f;
#pragma unroll
        for (int j = 0; j < KNBR; j++) {
            w[j] = __expf(logit[j] - m);
            s += w[j];
        }
        float inv = 1.f / s;
#pragma unroll
        for (int j = 0; j < KNBR; j++) w[j] *= inv;
    }

    float o = 0.f;
#pragma unroll
    for (int j = 0; j < KNBR; j++) {
        int kj = __shfl_sync(0xffffffffu, myIdx, j);
        float vv = (kj >= 0) ? g_v[(size_t)kj * EDIM + base] : 0.f;
        o = fmaf(w[j], vv, o);
    }
    g_attn[(size_t)q * EDIM + base] = o;

    if (write_w) {
#pragma unroll
        for (int j = 0; j < KNBR; j++)
            if (lane == j) sw[warp][j] = w[j];
        __syncthreads();
        if (threadIdx.x < KNBR) {
            float acc = 0.f;
#pragma unroll
            for (int h = 0; h < NH; h++) acc += sw[h][threadIdx.x];
            w_out[q * KNBR + threadIdx.x] = acc * 0.125f;  // /NH
        }
    }
}

// ---------------------------------------------------------------------------
extern "C" void kernel_launch(void* const* d_in, const int* in_sizes, int n_in,
                              void* d_out, int out_size)
{
    const float* q_in = (const float*)d_in[0];
    const float* k_in = (const float*)d_in[1];
    const float* v_in = (const float*)d_in[2];
    const int*   idx  = (const int*)  d_in[3];
    const float* Wall = (const float*)d_in[4];
    const float* ball = (const float*)d_in[5];
    const float* Wout = (const float*)d_in[6];
    const float* bout = (const float*)d_in[7];
    float* out = (float*)d_out;

    // 1) fused q/k/v projections (TF32 tensor cores)
    dim3 gproj(2, 512, 3);
    qkv_proj_kernel<<<gproj, 256>>>(q_in, k_in, v_in, Wall, ball);

    // 2) gather attention (+ averaged weights, second output)
    int write_w = (out_size >= QLEN * (EDIM + KNBR)) ? 1 : 0;
    attn_kernel<<<QLEN, 256>>>(idx, out + (size_t)QLEN * EDIM, write_w);

    // 3) output projection -> d_out[0 : Q*E]
    dim3 gout(2, 512, 1);
    outproj_kernel<<<gout, 256>>>(Wout, bout, out);
}

// round 5
// speedup vs baseline: 2.5556x; 1.5873x over previous
#include <cuda_runtime.h>
#include <math_constants.h>
#include <cstdint>

#define QLEN  65536
#define EDIM  256
#define NH    8
#define DHEAD 32
#define KNBR  16

// Scratch (allocation-free rule: __device__ globals)
__device__ float g_q[(size_t)QLEN * EDIM];
__device__ float g_k[(size_t)QLEN * EDIM];
__device__ float g_v[(size_t)QLEN * EDIM];
__device__ float g_attn[(size_t)QLEN * EDIM];
__device__ uint32_t g_wt[4 * 256 * 256];   // pre-converted tf32 weights: q,k,v,out

// ---------------------------------------------------------------------------
// PTX helpers
// ---------------------------------------------------------------------------
__device__ __forceinline__ uint32_t f2tf32(float x) {
    uint32_t r;
    asm("cvt.rna.tf32.f32 %0, %1;" : "=r"(r) : "f"(x));
    return r;
}

__device__ __forceinline__ void mma_tf32(float c[4], const uint32_t a[4], const uint32_t b[2]) {
    asm volatile(
        "mma.sync.aligned.m16n8k8.row.col.f32.tf32.tf32.f32 "
        "{%0,%1,%2,%3}, {%4,%5,%6,%7}, {%8,%9}, {%0,%1,%2,%3};"
        : "+f"(c[0]), "+f"(c[1]), "+f"(c[2]), "+f"(c[3])
        : "r"(a[0]), "r"(a[1]), "r"(a[2]), "r"(a[3]), "r"(b[0]), "r"(b[1]));
}

__device__ __forceinline__ void cp_async16(void* dst, const void* src) {
    uint32_t d = (uint32_t)__cvta_generic_to_shared(dst);
    asm volatile("cp.async.cg.shared.global [%0], [%1], 16;" :: "r"(d), "l"(src));
}
__device__ __forceinline__ void cp_commit() { asm volatile("cp.async.commit_group;"); }
__device__ __forceinline__ void cp_wait0() { asm volatile("cp.async.wait_group 0;"); }
__device__ __forceinline__ void cp_wait1() { asm volatile("cp.async.wait_group 1;"); }

__device__ __forceinline__ void ldsm_x4(uint32_t r[4], const uint32_t* saddr) {
    uint32_t a = (uint32_t)__cvta_generic_to_shared(saddr);
    asm volatile("ldmatrix.sync.aligned.m8n8.x4.shared.b16 {%0,%1,%2,%3}, [%4];"
        : "=r"(r[0]), "=r"(r[1]), "=r"(r[2]), "=r"(r[3]) : "r"(a));
}

// ---------------------------------------------------------------------------
// Weight pre-convert: fp32 -> tf32 bits (256KB total, trivial kernel)
// layout: g_wt[0:64K)=Wq, [64K:128K)=Wk, [128K:192K)=Wv, [192K:256K)=Wout
// ---------------------------------------------------------------------------
__global__ void cvt_weights_kernel(const float* __restrict__ Wall,
                                   const float* __restrict__ Wout)
{
    int i = blockIdx.x * 256 + threadIdx.x;
    float v = (i < 3 * 65536) ? Wall[i] : Wout[i - 3 * 65536];
    g_wt[i] = f2tf32(v);
}

// ---------------------------------------------------------------------------
// TF32 GEMM v2: cp.async double-buffered, ldmatrix fragments.
// C[M,256] = (A[M,256] @ W[256,256]^T + bias) * scale
// Block 128x128, BK=32, 2 smem stages, 256 threads = 8 warps (4M x 2N),
// warp tile 32x64 = 2x8 m16n8k8.
// ---------------------------------------------------------------------------
#define SST 36            // padded row stride in words (ldmatrix conflict-free)
#define STAGE_WORDS 9216  // (128*36)*2 arrays per stage

__device__ __forceinline__ void gemm_prefetch(const float* __restrict__ A,
                                              const uint32_t* __restrict__ Wt,
                                              uint32_t* sA, uint32_t* sB,
                                              int mBase, int nBase, int kc,
                                              int prow, int kq)
{
#pragma unroll
    for (int p = 0; p < 4; p++) {
        int r = prow + p * 32;
        cp_async16(sA + r * SST + kq * 4, A  + (size_t)(mBase + r) * 256 + kc + kq * 4);
        cp_async16(sB + r * SST + kq * 4, Wt + (size_t)(nBase + r) * 256 + kc + kq * 4);
    }
}

__device__ __forceinline__ void gemm256_v2(const float* __restrict__ A,
                                           const uint32_t* __restrict__ Wt,
                                           const float* __restrict__ bias,
                                           float* __restrict__ C,
                                           float scale)
{
    extern __shared__ uint32_t sm[];   // 2 stages x (A 4608 + B 4608) words

    const int tid   = threadIdx.x;
    const int lane  = tid & 31;
    const int warp  = tid >> 5;
    const int g     = lane >> 2;
    const int t     = lane & 3;
    const int warpM = warp >> 1;
    const int warpN = warp & 1;
    const int mBase = blockIdx.y * 128;
    const int nBase = blockIdx.x * 128;
    const int kq    = tid & 7;
    const int prow  = tid >> 3;

    // ldmatrix per-lane address components (4 tiles: [m0..7|m8..15] x [k0|k0+4])
    const int lq = lane >> 3;            // tile id 0..3
    const int lr = lane & 7;             // row within tile
    const int aRow  = warpM * 32 + (lq & 1) * 8 + lr;
    const int bRowB = warpN * 64 + (lq & 1) * 8 + lr;
    const int colOf = (lq >> 1) * 4;

    float acc[2][8][4];
#pragma unroll
    for (int ma = 0; ma < 2; ma++)
#pragma unroll
        for (int na = 0; na < 8; na++)
#pragma unroll
            for (int i = 0; i < 4; i++) acc[ma][na][i] = 0.f;

    gemm_prefetch(A, Wt, sm, sm + 4608, mBase, nBase, 0, prow, kq);
    cp_commit();

    for (int it = 0; it < 8; ++it) {
        if (it < 7) {
            uint32_t* st = sm + ((it + 1) & 1) * STAGE_WORDS;
            gemm_prefetch(A, Wt, st, st + 4608, mBase, nBase, (it + 1) * 32, prow, kq);
            cp_commit();
            cp_wait1();
        } else {
            cp_wait0();
        }
        __syncthreads();

        uint32_t* sA = sm + (it & 1) * STAGE_WORDS;
        uint32_t* sB = sA + 4608;

#pragma unroll
        for (int ks = 0; ks < 4; ks++) {
            const int k0 = ks * 8;
            uint32_t a[2][4];
#pragma unroll
            for (int ma = 0; ma < 2; ma++) {
                ldsm_x4(a[ma], sA + (aRow + ma * 16) * SST + k0 + colOf);
#pragma unroll
                for (int i = 0; i < 4; i++)
                    a[ma][i] = f2tf32(__uint_as_float(a[ma][i]));
            }
            uint32_t b[8][2];
#pragma unroll
            for (int n2 = 0; n2 < 4; n2++) {
                uint32_t r4[4];
                ldsm_x4(r4, sB + (bRowB + n2 * 16) * SST + k0 + colOf);
                b[2 * n2][0] = r4[0]; b[2 * n2 + 1][0] = r4[1];
                b[2 * n2][1] = r4[2]; b[2 * n2 + 1][1] = r4[3];
            }
#pragma unroll
            for (int ma = 0; ma < 2; ma++)
#pragma unroll
                for (int na = 0; na < 8; na++)
                    mma_tf32(acc[ma][na], a[ma], b[na]);
        }
        __syncthreads();
    }

    // epilogue: bias + scale, float2 stores
#pragma unroll
    for (int ma = 0; ma < 2; ma++) {
        int row0 = mBase + warpM * 32 + ma * 16 + g;
#pragma unroll
        for (int na = 0; na < 8; na++) {
            int col = nBase + warpN * 64 + na * 8 + t * 2;
            float2 bb = *(const float2*)(bias + col);
            float2 o0, o1;
            o0.x = (acc[ma][na][0] + bb.x) * scale;
            o0.y = (acc[ma][na][1] + bb.y) * scale;
            o1.x = (acc[ma][na][2] + bb.x) * scale;
            o1.y = (acc[ma][na][3] + bb.y) * scale;
            *(float2*)(C + (size_t)row0 * 256 + col) = o0;
            *(float2*)(C + (size_t)(row0 + 8) * 256 + col) = o1;
        }
    }
}

__global__ __launch_bounds__(256, 2)
void qkv_proj_kernel(const float* __restrict__ q_in,
                     const float* __restrict__ k_in,
                     const float* __restrict__ v_in,
                     const float* __restrict__ ball)
{
    const float* A;
    const float* b;
    float* C;
    float scale;
    const uint32_t* Wt;
    if (blockIdx.z == 0) {
        A = q_in; Wt = g_wt;              b = ball;       C = g_q;
        scale = 0.17677669529663687f;     // 1/sqrt(32)
    } else if (blockIdx.z == 1) {
        A = k_in; Wt = g_wt + 65536;      b = ball + 256; C = g_k; scale = 1.f;
    } else {
        A = v_in; Wt = g_wt + 131072;     b = ball + 512; C = g_v; scale = 1.f;
    }
    gemm256_v2(A, Wt, b, C, scale);
}

__global__ __launch_bounds__(256, 2)
void outproj_kernel(const float* __restrict__ bout, float* __restrict__ out)
{
    gemm256_v2(g_attn, g_wt + 196608, bout, out, 1.f);
}

// ---------------------------------------------------------------------------
// Attention v2: 1 block (256 thr) per query. Low-shfl design:
//  logit stage: warp w handles neighbors j=2w,2w+1; lane covers 8 contiguous
//    floats (head h=lane>>2, slice s=lane&3) -> 2 shfls per neighbor.
//  softmax: through smem [16][9] (conflict-free column reads).
//  V stage: thread <-> output element (coalesced 128B row reads, 0 shfls).
// ---------------------------------------------------------------------------
__global__ __launch_bounds__(256)
void attn_kernel(const int* __restrict__ idx,
                 float* __restrict__ w_out,
                 int write_w)
{
    const int q    = blockIdx.x;
    const int tid  = threadIdx.x;
    const int lane = tid & 31;
    const int warp = tid >> 5;

    __shared__ int   sidx[KNBR];
    __shared__ float sq[EDIM];
    __shared__ float slog[KNBR][9];
    __shared__ float sexp[KNBR][9];
    __shared__ float sw[KNBR][9];

    if (tid < KNBR) sidx[tid] = idx[q * KNBR + tid];
    if (tid < 64) ((float4*)sq)[tid] = ((const float4*)(g_q + (size_t)q * EDIM))[tid];
    __syncthreads();

    // ---- logits ----
    const int h   = lane >> 2;        // head 0..7
    const int s   = lane & 3;         // quarter within head
    const int off = h * 32 + s * 8;   // lane*8: warp reads a full contiguous row
    float qr[8];
    *(float4*)&qr[0] = *(const float4*)(sq + off);
    *(float4*)&qr[4] = *(const float4*)(sq + off + 4);

#pragma unroll
    for (int b = 0; b < 2; b++) {
        int j   = warp * 2 + b;
        int kj  = sidx[j];
        int kjc = max(kj, 0);
        const float4* kr = (const float4*)(g_k + (size_t)kjc * EDIM + off);
        float4 k0 = kr[0], k1 = kr[1];
        float p;
        p = qr[0] * k0.x;
        p = fmaf(qr[1], k0.y, p);
        p = fmaf(qr[2], k0.z, p);
        p = fmaf(qr[3], k0.w, p);
        p = fmaf(qr[4], k1.x, p);
        p = fmaf(qr[5], k1.y, p);
        p = fmaf(qr[6], k1.z, p);
        p = fmaf(qr[7], k1.w, p);
        p += __shfl_xor_sync(0xffffffffu, p, 1);
        p += __shfl_xor_sync(0xffffffffu, p, 2);
        if (s == 0) slog[j][h] = (kj >= 0) ? p : -CUDART_INF_F;
    }
    __syncthreads();

    // ---- softmax (threads 0..127: thread <-> (j,h)) ----
    float m = -CUDART_INF_F, e = 0.f;
    int jj = 0, hh = 0;
    if (tid < 128) {
        jj = tid >> 3; hh = tid & 7;
#pragma unroll
        for (int x = 0; x < KNBR; x++) m = fmaxf(m, slog[x][hh]);
        if (m != -CUDART_INF_F) e = __expf(slog[jj][hh] - m);  // exp(-inf)=0
        sexp[jj][hh] = e;
    }
    __syncthreads();
    if (tid < 128) {
        float S = 0.f;
#pragma unroll
        for (int x = 0; x < KNBR; x++) S += sexp[x][hh];
        float w = (m != -CUDART_INF_F) ? e / S : 0.f;
        sw[jj][hh] = w;
    }
    __syncthreads();

    // ---- weighted V gather: thread <-> output element tid ----
    const int h2 = tid >> 5;
    float o = 0.f;
#pragma unroll
    for (int j = 0; j < KNBR; j++) {
        int kjc = max(sidx[j], 0);
        float wv = sw[j][h2];
        o = fmaf(wv, g_v[(size_t)kjc * EDIM + tid], o);
    }
    g_attn[(size_t)q * EDIM + tid] = o;

    if (write_w && tid < KNBR) {
        float acc = 0.f;
#pragma unroll
        for (int x = 0; x < NH; x++) acc += sw[tid][x];
        w_out[q * KNBR + tid] = acc * 0.125f;
    }
}

// ---------------------------------------------------------------------------
extern "C" void kernel_launch(void* const* d_in, const int* in_sizes, int n_in,
                              void* d_out, int out_size)
{
    const float* q_in = (const float*)d_in[0];
    const float* k_in = (const float*)d_in[1];
    const float* v_in = (const float*)d_in[2];
    const int*   idx  = (const int*)  d_in[3];
    const float* Wall = (const float*)d_in[4];
    const float* ball = (const float*)d_in[5];
    const float* Wout = (const float*)d_in[6];
    const float* bout = (const float*)d_in[7];
    float* out = (float*)d_out;

    const int SMEM = 2 * STAGE_WORDS * 4;   // 73728 B
    cudaFuncSetAttribute(qkv_proj_kernel, cudaFuncAttributeMaxDynamicSharedMemorySize, SMEM);
    cudaFuncSetAttribute(outproj_kernel,  cudaFuncAttributeMaxDynamicSharedMemorySize, SMEM);

    // 0) weights -> tf32 bits (256K elements)
    cvt_weights_kernel<<<1024, 256>>>(Wall, Wout);

    // 1) fused q/k/v projections
    dim3 gproj(2, 512, 3);
    qkv_proj_kernel<<<gproj, 256, SMEM>>>(q_in, k_in, v_in, ball);

    // 2) gather attention (+ averaged weights, second output)
    int write_w = (out_size >= QLEN * (EDIM + KNBR)) ? 1 : 0;
    attn_kernel<<<QLEN, 256>>>(idx, out + (size_t)QLEN * EDIM, write_w);

    // 3) output projection -> d_out[0 : Q*E]
    dim3 gout(2, 512, 1);
    outproj_kernel<<<gout, 256, SMEM>>>(bout, out);
}